// round 1
// baseline (speedup 1.0000x reference)
#include <cuda_runtime.h>
#include <math.h>

// Problem constants (fixed shapes per metadata)
#define NN      20000
#define EE      160000
#define ETOT    (NN + EE)      // 180000 (edges + self loops)
#define INF_    64             // node feature dim
#define EC      16             // edge feature dim
#define KD      80             // IN + EC
#define TSTEPS  4
#define NB      10             // degree buckets
#define NG      64             // num graphs
#define TM      128            // edges per tile
#define TPB     256
#define MIS     81             // padded mi row stride (bank-conflict free)
#define NTILE_MAX (((ETOT + TM - 1) / TM) + NB)   // upper bound on tiles
#define PERM_PAD  (ETOT + NB * TM)

#define MSG_SMEM ((KD*INF_ + TM*MIS) * 4 + 3 * TM * 4)
#define MLP_SMEM ((NG*10 + NG*128 + NG*64) * 4)

// ---------------- device scratch (no allocations allowed) ----------------
__device__ int   g_deg[NN];
__device__ int   g_count[NB];
__device__ int   g_cursor[NB];
__device__ int   g_tileStart[NB + 1];
__device__ int   g_perm[PERM_PAD];
__device__ float g_xA[NN * INF_];
__device__ float g_xB[NN * INF_];
__device__ float g_pooled[NG * 10];

// ---------------- preprocessing kernels ----------------
__global__ void k_init() {
    int i = blockIdx.x * blockDim.x + threadIdx.x;
    if (i < PERM_PAD) g_perm[i] = -1;
    if (i < NN)       g_deg[i] = 0;
    if (i < NB)       { g_count[i] = 0; g_cursor[i] = 0; }
    if (i < NG * 10)  g_pooled[i] = 0.f;
}

__global__ void k_deg(const int* __restrict__ ei) {
    int e = blockIdx.x * blockDim.x + threadIdx.x;
    if (e < EE) atomicAdd(&g_deg[ei[e]], 1);
}

__device__ __forceinline__ int edge_bucket(const int* __restrict__ ei, int e) {
    int s = (e < EE) ? ei[e] : (e - EE);
    int d = g_deg[s] + 1;                 // +1 self loop
    return min(d, NB) - 1;
}

__global__ void k_count(const int* __restrict__ ei) {
    int e = blockIdx.x * blockDim.x + threadIdx.x;
    if (e < ETOT) atomicAdd(&g_count[edge_bucket(ei, e)], 1);
}

__global__ void k_scan() {
    if (threadIdx.x == 0 && blockIdx.x == 0) {
        int acc = 0;
        for (int b = 0; b < NB; b++) {
            g_tileStart[b] = acc;
            acc += (g_count[b] + TM - 1) / TM;
        }
        g_tileStart[NB] = acc;
    }
}

__global__ void k_scatter(const int* __restrict__ ei) {
    int e = blockIdx.x * blockDim.x + threadIdx.x;
    if (e < ETOT) {
        int b = edge_bucket(ei, e);
        int pos = atomicAdd(&g_cursor[b], 1);
        g_perm[g_tileStart[b] * TM + pos] = e;
    }
}

__global__ void k_zero(float* __restrict__ p, int n4) {
    int i = blockIdx.x * blockDim.x + threadIdx.x;
    if (i < n4) ((float4*)p)[i] = make_float4(0.f, 0.f, 0.f, 0.f);
}

// ---------------- message kernel: one 128-edge tile, shared bucket weight ----------------
__global__ __launch_bounds__(TPB) void k_msg(
    const float* __restrict__ xin, const float* __restrict__ ea,
    const int* __restrict__ ei, const float* __restrict__ Wt,   // W_msg[t] base: [NB][KD][INF_]
    float* __restrict__ xout)
{
    extern __shared__ float sm[];
    float* Wsm = sm;                        // KD*INF_ = 5120
    float* miS = sm + KD * INF_;            // TM*MIS
    int*   srcS = (int*)(miS + TM * MIS);
    int*   dstS = srcS + TM;
    int*   eS   = dstS + TM;

    const int tid = threadIdx.x;
    const int tile = blockIdx.x;

    __shared__ int s_bucket, s_total;
    if (tid == 0) {
        int total = g_tileStart[NB];
        s_total = total;
        int b = 0;
        if (tile < total) { while (tile >= g_tileStart[b + 1]) b++; }
        s_bucket = b;
    }
    __syncthreads();
    if (tile >= s_total) return;
    const int bucket = s_bucket;

    // stage the bucket's weight matrix [KD][INF_]
    const float4* Wg = (const float4*)(Wt + bucket * KD * INF_);
    #pragma unroll
    for (int i = tid; i < KD * INF_ / 4; i += TPB) ((float4*)Wsm)[i] = Wg[i];

    // edge metadata
    const int base = tile * TM;
    for (int r = tid; r < TM; r += TPB) {
        int e = g_perm[base + r];
        int s = -1, d = -1;
        if (e >= 0) {
            if (e < EE) { s = ei[e]; d = ei[EE + e]; }
            else        { s = e - EE; d = s; }
        }
        srcS[r] = s; dstS[r] = d; eS[r] = e;
    }
    __syncthreads();

    // gather mi rows: [x[src] (64) | edge_attr (16, zero for self loops/pad)]
    for (int idx = tid; idx < TM * KD; idx += TPB) {
        int r = idx / KD, k = idx - r * KD;
        int e = eS[r];
        float v = 0.f;
        if (e >= 0) {
            if (k < INF_)    v = xin[srcS[r] * INF_ + k];
            else if (e < EE) v = ea[e * EC + (k - INF_)];
        }
        miS[r * MIS + k] = v;
    }
    __syncthreads();

    // 128x64 tile: thread (ty,tx) -> rows ty*8..+8, cols {0,16,32,48}+tx
    const int tx = tid & 15;
    const int ty = tid >> 4;
    float acc[8][4];
    #pragma unroll
    for (int i = 0; i < 8; i++)
        #pragma unroll
        for (int j = 0; j < 4; j++) acc[i][j] = 0.f;

    const float* mp = miS + ty * 8 * MIS;
    #pragma unroll 2
    for (int k = 0; k < KD; k++) {
        float b0 = Wsm[k * INF_ + tx];
        float b1 = Wsm[k * INF_ + tx + 16];
        float b2 = Wsm[k * INF_ + tx + 32];
        float b3 = Wsm[k * INF_ + tx + 48];
        #pragma unroll
        for (int i = 0; i < 8; i++) {
            float a = mp[i * MIS + k];
            acc[i][0] += a * b0; acc[i][1] += a * b1;
            acc[i][2] += a * b2; acc[i][3] += a * b3;
        }
    }

    // sigmoid + scatter-add to destination nodes
    #pragma unroll
    for (int i = 0; i < 8; i++) {
        int r = ty * 8 + i;
        int d = dstS[r];
        if (d >= 0) {
            #pragma unroll
            for (int j = 0; j < 4; j++) {
                float v = 1.f / (1.f + __expf(-acc[i][j]));
                atomicAdd(&xout[d * INF_ + j * 16 + tx], v);
            }
        }
    }
}

// ---------------- readout: softmax heads + pooled accumulation ----------------
__global__ __launch_bounds__(TPB) void k_readout(
    const float* __restrict__ x, const float* __restrict__ Wread,
    const int* __restrict__ batch)
{
    __shared__ float Ws[TSTEPS * INF_ * 10];   // 10240 B
    for (int i = threadIdx.x; i < TSTEPS * INF_ * 10; i += TPB) Ws[i] = Wread[i];
    __syncthreads();

    int n = blockIdx.x * blockDim.x + threadIdx.x;
    if (n >= NN) return;

    float xr[INF_];
    const float4* xp = (const float4*)(x + n * INF_);
    #pragma unroll
    for (int q = 0; q < INF_ / 4; q++) {
        float4 f = xp[q];
        xr[q * 4 + 0] = f.x; xr[q * 4 + 1] = f.y; xr[q * 4 + 2] = f.z; xr[q * 4 + 3] = f.w;
    }

    float accq[10];
    #pragma unroll
    for (int j = 0; j < 10; j++) accq[j] = 0.f;

    for (int t = 0; t < TSTEPS; t++) {
        float l[10];
        #pragma unroll
        for (int j = 0; j < 10; j++) l[j] = 0.f;
        const float* W = Ws + t * INF_ * 10;
        #pragma unroll 4
        for (int k = 0; k < INF_; k++) {
            float xv = xr[k];
            #pragma unroll
            for (int j = 0; j < 10; j++) l[j] += xv * W[k * 10 + j];
        }
        float m = l[0];
        #pragma unroll
        for (int j = 1; j < 10; j++) m = fmaxf(m, l[j]);
        float s = 0.f;
        #pragma unroll
        for (int j = 0; j < 10; j++) { l[j] = __expf(l[j] - m); s += l[j]; }
        float inv = 1.f / s;
        #pragma unroll
        for (int j = 0; j < 10; j++) accq[j] += l[j] * inv;
    }

    int g = batch[n];
    #pragma unroll
    for (int j = 0; j < 10; j++) atomicAdd(&g_pooled[g * 10 + j], accq[j]);
}

// ---------------- final MLP: 10 -> 128 -> 64 -> 1 ----------------
__global__ __launch_bounds__(TPB) void k_mlp(
    const float* __restrict__ fc1w, const float* __restrict__ fc1b,
    const float* __restrict__ fc2w, const float* __restrict__ fc2b,
    const float* __restrict__ fc3w, const float* __restrict__ fc3b,
    float* __restrict__ out)
{
    extern __shared__ float sm[];
    float* P  = sm;              // NG*10
    float* H1 = P + NG * 10;     // NG*128
    float* H2 = H1 + NG * 128;   // NG*64
    int tid = threadIdx.x;

    for (int i = tid; i < NG * 10; i += TPB) P[i] = g_pooled[i];
    __syncthreads();

    for (int idx = tid; idx < NG * 128; idx += TPB) {
        int g = idx >> 7, j = idx & 127;
        float a = fc1b[j];
        #pragma unroll
        for (int k = 0; k < 10; k++) a += P[g * 10 + k] * fc1w[k * 128 + j];
        H1[idx] = a > 0.f ? a : 0.01f * a;
    }
    __syncthreads();

    for (int idx = tid; idx < NG * 64; idx += TPB) {
        int g = idx >> 6, j = idx & 63;
        float a = fc2b[j];
        #pragma unroll 8
        for (int k = 0; k < 128; k++) a += H1[g * 128 + k] * fc2w[k * 64 + j];
        H2[idx] = a > 0.f ? a : 0.01f * a;
    }
    __syncthreads();

    for (int g = tid; g < NG; g += TPB) {
        float a = fc3b[0];
        #pragma unroll 8
        for (int k = 0; k < 64; k++) a += H2[g * 64 + k] * fc3w[k];
        out[g] = a > 0.f ? a : 0.01f * a;
    }
}

// ---------------- launch ----------------
extern "C" void kernel_launch(void* const* d_in, const int* in_sizes, int n_in,
                              void* d_out, int out_size)
{
    const float* x     = (const float*)d_in[0];
    const float* ea    = (const float*)d_in[1];
    const float* Wmsg  = (const float*)d_in[2];
    const float* Wread = (const float*)d_in[3];
    const float* fc1w  = (const float*)d_in[4];
    const float* fc1b  = (const float*)d_in[5];
    const float* fc2w  = (const float*)d_in[6];
    const float* fc2b  = (const float*)d_in[7];
    const float* fc3w  = (const float*)d_in[8];
    const float* fc3b  = (const float*)d_in[9];
    const int*   ei    = (const int*)d_in[10];
    const int*   batch = (const int*)d_in[11];
    float* out = (float*)d_out;

    cudaFuncSetAttribute(k_msg, cudaFuncAttributeMaxDynamicSharedMemorySize, MSG_SMEM);
    cudaFuncSetAttribute(k_mlp, cudaFuncAttributeMaxDynamicSharedMemorySize, MLP_SMEM);

    void *pA = nullptr, *pB = nullptr;
    cudaGetSymbolAddress(&pA, g_xA);
    cudaGetSymbolAddress(&pB, g_xB);

    k_init<<<(PERM_PAD + TPB - 1) / TPB, TPB>>>();
    k_deg<<<(EE + TPB - 1) / TPB, TPB>>>(ei);
    k_count<<<(ETOT + TPB - 1) / TPB, TPB>>>(ei);
    k_scan<<<1, 32>>>();
    k_scatter<<<(ETOT + TPB - 1) / TPB, TPB>>>(ei);

    const float* xin = x;
    for (int t = 0; t < TSTEPS; t++) {
        float* xo = (t % 2 == 0) ? (float*)pB : (float*)pA;
        k_zero<<<(NN * INF_ / 4 + TPB - 1) / TPB, TPB>>>(xo, NN * INF_ / 4);
        k_msg<<<NTILE_MAX, TPB, MSG_SMEM>>>(xin, ea, ei, Wmsg + (size_t)t * NB * KD * INF_, xo);
        xin = xo;
    }

    k_readout<<<(NN + TPB - 1) / TPB, TPB>>>(xin, Wread, batch);
    k_mlp<<<1, TPB, MLP_SMEM>>>(fc1w, fc1b, fc2w, fc2b, fc3w, fc3b, out);
}

// round 2
// speedup vs baseline: 1.0278x; 1.0278x over previous
#include <cuda_runtime.h>
#include <math.h>

// Problem constants (fixed shapes per metadata)
#define NN      20000
#define EE      160000
#define ETOT    (NN + EE)      // 180000 (edges + self loops)
#define INF_    64             // node feature dim
#define EC      16             // edge feature dim
#define KD      80             // IN + EC
#define TSTEPS  4
#define NB      10             // degree buckets
#define NG      64             // num graphs
#define TM      128            // edges per tile
#define TPB     256
#define MIS     84             // padded mi row stride (float4-friendly)
#define NTILE_MAX (((ETOT + TM - 1) / TM) + NB)
#define PERM_PAD  (ETOT + NB * TM)

#define MSG_SMEM ((KD*INF_ + TM*MIS) * 4 + 2 * TM * 4)
#define MLP_SMEM ((NG*10 + NG*128 + NG*64) * 4)

// ---------------- device scratch ----------------
__device__ int   g_deg[NN];
__device__ int   g_indeg[NN];
__device__ int   g_dptr[NN + 1];
__device__ int   g_dcur[NN];
__device__ int   g_dlist[EE];
__device__ int   g_count[NB];
__device__ int   g_cursor[NB];
__device__ int   g_tileStart[NB + 1];
__device__ int   g_perm[PERM_PAD];
__device__ float g_msgs[ETOT * INF_];       // per-edge messages (46MB)
__device__ float g_xA[NN * INF_];
__device__ float g_xB[NN * INF_];
__device__ float g_pooled[NG * 10];

// ---------------- preprocessing ----------------
__global__ void k_init() {
    int i = blockIdx.x * blockDim.x + threadIdx.x;
    if (i < PERM_PAD) g_perm[i] = -1;
    if (i < NN)       { g_deg[i] = 0; g_indeg[i] = 0; g_dcur[i] = 0; }
    if (i < NB)       { g_count[i] = 0; g_cursor[i] = 0; }
    if (i < NG * 10)  g_pooled[i] = 0.f;
}

__global__ void k_deg(const int* __restrict__ ei) {
    int e = blockIdx.x * blockDim.x + threadIdx.x;
    if (e < EE) {
        atomicAdd(&g_deg[ei[e]], 1);        // out-degree of src (bucket)
        atomicAdd(&g_indeg[ei[EE + e]], 1); // in-degree of dst (CSR)
    }
}

__device__ __forceinline__ int edge_bucket(const int* __restrict__ ei, int e) {
    int s = (e < EE) ? ei[e] : (e - EE);
    int d = g_deg[s] + 1;                   // +1 self loop
    return min(d, NB) - 1;
}

__global__ void k_count(const int* __restrict__ ei) {
    int e = blockIdx.x * blockDim.x + threadIdx.x;
    if (e < ETOT) atomicAdd(&g_count[edge_bucket(ei, e)], 1);
}

__global__ void k_scan() {
    if (threadIdx.x == 0 && blockIdx.x == 0) {
        int acc = 0;
        for (int b = 0; b < NB; b++) {
            g_tileStart[b] = acc;
            acc += (g_count[b] + TM - 1) / TM;
        }
        g_tileStart[NB] = acc;
    }
}

// exclusive scan of in-degrees -> g_dptr (single block, 1024 threads)
#define SCH 20   // ceil(20000/1024)
__global__ __launch_bounds__(1024) void k_dscan() {
    __shared__ int ssum[1024];
    int t = threadIdx.x;
    int lo = t * SCH, hi = min(lo + SCH, NN);
    int s = 0;
    for (int i = lo; i < hi; i++) s += g_indeg[i];
    ssum[t] = s;
    __syncthreads();
    for (int off = 1; off < 1024; off <<= 1) {
        int v = 0;
        if (t >= off) v = ssum[t - off];
        __syncthreads();
        if (t >= off) ssum[t] += v;
        __syncthreads();
    }
    int pre = (t == 0) ? 0 : ssum[t - 1];
    for (int i = lo; i < hi; i++) {
        int d = g_indeg[i];
        g_dptr[i] = pre;
        pre += d;
    }
    if (lo < NN && hi == NN) g_dptr[NN] = pre;
}

__global__ void k_scatter(const int* __restrict__ ei) {
    int e = blockIdx.x * blockDim.x + threadIdx.x;
    if (e < ETOT) {
        int b = edge_bucket(ei, e);
        int pos = atomicAdd(&g_cursor[b], 1);
        g_perm[g_tileStart[b] * TM + pos] = e;
    }
}

__global__ void k_dscatter(const int* __restrict__ ei) {
    int e = blockIdx.x * blockDim.x + threadIdx.x;
    if (e < EE) {
        int d = ei[EE + e];
        int pos = atomicAdd(&g_dcur[d], 1);
        g_dlist[g_dptr[d] + pos] = e;
    }
}

// ---------------- phase 1: grouped GEMM -> per-edge messages ----------------
__global__ __launch_bounds__(TPB, 2) void k_msg(
    const float* __restrict__ xin, const float* __restrict__ ea,
    const int* __restrict__ ei, const float* __restrict__ Wt)   // W_msg[t]: [NB][KD][INF_]
{
    extern __shared__ float sm[];
    float* Wsm = sm;                         // KD*INF_ = 5120
    float* miS = sm + KD * INF_;             // TM*MIS = 10752
    int*   srcS = (int*)(miS + TM * MIS);
    int*   eS   = srcS + TM;

    const int tid = threadIdx.x;
    const int tile = blockIdx.x;

    __shared__ int s_bucket, s_total;
    if (tid == 0) {
        int total = g_tileStart[NB];
        s_total = total;
        int b = 0;
        if (tile < total) { while (tile >= g_tileStart[b + 1]) b++; }
        s_bucket = b;
    }
    __syncthreads();
    if (tile >= s_total) return;
    const int bucket = s_bucket;

    // stage bucket weight [KD][INF_]
    const float4* Wg = (const float4*)(Wt + bucket * KD * INF_);
    #pragma unroll
    for (int i = tid; i < KD * INF_ / 4; i += TPB) ((float4*)Wsm)[i] = Wg[i];

    // edge metadata
    const int base = tile * TM;
    for (int r = tid; r < TM; r += TPB) {
        int e = g_perm[base + r];
        int s = 0;
        if (e >= 0) s = (e < EE) ? ei[e] : (e - EE);
        srcS[r] = s; eS[r] = e;
    }
    __syncthreads();

    // gather mi rows as float4: [x[src] 16x f4 | ea 4x f4]
    float4* miS4 = (float4*)miS;
    const float4* xin4 = (const float4*)xin;
    const float4* ea4  = (const float4*)ea;
    for (int idx = tid; idx < TM * 20; idx += TPB) {
        int r = idx / 20, q = idx - r * 20;
        int e = eS[r];
        float4 v = make_float4(0.f, 0.f, 0.f, 0.f);
        if (e >= 0) {
            if (q < 16)      v = xin4[srcS[r] * 16 + q];
            else if (e < EE) v = ea4[e * 4 + (q - 16)];
        }
        miS4[(r * MIS) / 4 + q] = v;   // MIS divisible by 4
    }
    __syncthreads();

    // 128x64 tile: thread (ty,tx) -> rows ty*8..+8, cols tx*4..+4
    const int tx = tid & 15;
    const int ty = tid >> 4;
    float acc[8][4];
    #pragma unroll
    for (int i = 0; i < 8; i++)
        #pragma unroll
        for (int j = 0; j < 4; j++) acc[i][j] = 0.f;

    const float4* Ap = (const float4*)(miS + ty * 8 * MIS);
    const float4* Bp = (const float4*)(Wsm) + tx;      // Wsm[k*64 + tx*4]

    #pragma unroll 4
    for (int kk = 0; kk < KD; kk += 4) {
        float4 b0 = Bp[(kk + 0) * 16];
        float4 b1 = Bp[(kk + 1) * 16];
        float4 b2 = Bp[(kk + 2) * 16];
        float4 b3 = Bp[(kk + 3) * 16];
        #pragma unroll
        for (int i = 0; i < 8; i++) {
            float4 a = Ap[(i * MIS + kk) / 4];
            acc[i][0] += a.x * b0.x + a.y * b1.x + a.z * b2.x + a.w * b3.x;
            acc[i][1] += a.x * b0.y + a.y * b1.y + a.z * b2.y + a.w * b3.y;
            acc[i][2] += a.x * b0.z + a.y * b1.z + a.z * b2.z + a.w * b3.z;
            acc[i][3] += a.x * b0.w + a.y * b1.w + a.z * b2.w + a.w * b3.w;
        }
    }

    // sigmoid + store per-edge message rows (coalesced float4)
    #pragma unroll
    for (int i = 0; i < 8; i++) {
        int r = ty * 8 + i;
        int e = eS[r];
        if (e >= 0) {
            float4 v;
            v.x = 1.f / (1.f + __expf(-acc[i][0]));
            v.y = 1.f / (1.f + __expf(-acc[i][1]));
            v.z = 1.f / (1.f + __expf(-acc[i][2]));
            v.w = 1.f / (1.f + __expf(-acc[i][3]));
            ((float4*)g_msgs)[e * 16 + tx] = v;
        }
    }
}

// ---------------- phase 2: aggregate messages by dst (CSR, no atomics) ----------------
__global__ __launch_bounds__(TPB) void k_aggr(float* __restrict__ xout) {
    int node = blockIdx.x * 4 + (threadIdx.x >> 6);
    int lane = threadIdx.x & 63;
    if (node >= NN) return;
    float s = g_msgs[(EE + node) * INF_ + lane];   // self loop message
    int beg = g_dptr[node], end = g_dptr[node + 1];
    for (int i = beg; i < end; i++) {
        int e = g_dlist[i];
        s += g_msgs[e * INF_ + lane];
    }
    xout[node * INF_ + lane] = s;
}

// ---------------- readout ----------------
__global__ __launch_bounds__(TPB) void k_readout(
    const float* __restrict__ x, const float* __restrict__ Wread,
    const int* __restrict__ batch)
{
    __shared__ float Ws[TSTEPS * INF_ * 10];
    for (int i = threadIdx.x; i < TSTEPS * INF_ * 10; i += TPB) Ws[i] = Wread[i];
    __syncthreads();

    int n = blockIdx.x * blockDim.x + threadIdx.x;
    if (n >= NN) return;

    float xr[INF_];
    const float4* xp = (const float4*)(x + n * INF_);
    #pragma unroll
    for (int q = 0; q < INF_ / 4; q++) {
        float4 f = xp[q];
        xr[q * 4 + 0] = f.x; xr[q * 4 + 1] = f.y; xr[q * 4 + 2] = f.z; xr[q * 4 + 3] = f.w;
    }

    float accq[10];
    #pragma unroll
    for (int j = 0; j < 10; j++) accq[j] = 0.f;

    for (int t = 0; t < TSTEPS; t++) {
        float l[10];
        #pragma unroll
        for (int j = 0; j < 10; j++) l[j] = 0.f;
        const float* W = Ws + t * INF_ * 10;
        #pragma unroll 4
        for (int k = 0; k < INF_; k++) {
            float xv = xr[k];
            #pragma unroll
            for (int j = 0; j < 10; j++) l[j] += xv * W[k * 10 + j];
        }
        float m = l[0];
        #pragma unroll
        for (int j = 1; j < 10; j++) m = fmaxf(m, l[j]);
        float ssum = 0.f;
        #pragma unroll
        for (int j = 0; j < 10; j++) { l[j] = __expf(l[j] - m); ssum += l[j]; }
        float inv = 1.f / ssum;
        #pragma unroll
        for (int j = 0; j < 10; j++) accq[j] += l[j] * inv;
    }

    int g = batch[n];
    #pragma unroll
    for (int j = 0; j < 10; j++) atomicAdd(&g_pooled[g * 10 + j], accq[j]);
}

// ---------------- final MLP: 10 -> 128 -> 64 -> 1 ----------------
__global__ __launch_bounds__(TPB) void k_mlp(
    const float* __restrict__ fc1w, const float* __restrict__ fc1b,
    const float* __restrict__ fc2w, const float* __restrict__ fc2b,
    const float* __restrict__ fc3w, const float* __restrict__ fc3b,
    float* __restrict__ out)
{
    extern __shared__ float sm[];
    float* P  = sm;
    float* H1 = P + NG * 10;
    float* H2 = H1 + NG * 128;
    int tid = threadIdx.x;

    for (int i = tid; i < NG * 10; i += TPB) P[i] = g_pooled[i];
    __syncthreads();

    for (int idx = tid; idx < NG * 128; idx += TPB) {
        int g = idx >> 7, j = idx & 127;
        float a = fc1b[j];
        #pragma unroll
        for (int k = 0; k < 10; k++) a += P[g * 10 + k] * fc1w[k * 128 + j];
        H1[idx] = a > 0.f ? a : 0.01f * a;
    }
    __syncthreads();

    for (int idx = tid; idx < NG * 64; idx += TPB) {
        int g = idx >> 6, j = idx & 63;
        float a = fc2b[j];
        #pragma unroll 8
        for (int k = 0; k < 128; k++) a += H1[g * 128 + k] * fc2w[k * 64 + j];
        H2[idx] = a > 0.f ? a : 0.01f * a;
    }
    __syncthreads();

    for (int g = tid; g < NG; g += TPB) {
        float a = fc3b[0];
        #pragma unroll 8
        for (int k = 0; k < 64; k++) a += H2[g * 64 + k] * fc3w[k];
        out[g] = a > 0.f ? a : 0.01f * a;
    }
}

// ---------------- launch ----------------
extern "C" void kernel_launch(void* const* d_in, const int* in_sizes, int n_in,
                              void* d_out, int out_size)
{
    const float* x     = (const float*)d_in[0];
    const float* ea    = (const float*)d_in[1];
    const float* Wmsg  = (const float*)d_in[2];
    const float* Wread = (const float*)d_in[3];
    const float* fc1w  = (const float*)d_in[4];
    const float* fc1b  = (const float*)d_in[5];
    const float* fc2w  = (const float*)d_in[6];
    const float* fc2b  = (const float*)d_in[7];
    const float* fc3w  = (const float*)d_in[8];
    const float* fc3b  = (const float*)d_in[9];
    const int*   ei    = (const int*)d_in[10];
    const int*   batch = (const int*)d_in[11];
    float* out = (float*)d_out;

    cudaFuncSetAttribute(k_msg, cudaFuncAttributeMaxDynamicSharedMemorySize, MSG_SMEM);
    cudaFuncSetAttribute(k_mlp, cudaFuncAttributeMaxDynamicSharedMemorySize, MLP_SMEM);

    void *pA = nullptr, *pB = nullptr;
    cudaGetSymbolAddress(&pA, g_xA);
    cudaGetSymbolAddress(&pB, g_xB);

    k_init<<<(PERM_PAD + TPB - 1) / TPB, TPB>>>();
    k_deg<<<(EE + TPB - 1) / TPB, TPB>>>(ei);
    k_count<<<(ETOT + TPB - 1) / TPB, TPB>>>(ei);
    k_scan<<<1, 32>>>();
    k_dscan<<<1, 1024>>>();
    k_scatter<<<(ETOT + TPB - 1) / TPB, TPB>>>(ei);
    k_dscatter<<<(EE + TPB - 1) / TPB, TPB>>>(ei);

    const float* xin = x;
    for (int t = 0; t < TSTEPS; t++) {
        float* xo = (t % 2 == 0) ? (float*)pB : (float*)pA;
        k_msg<<<NTILE_MAX, TPB, MSG_SMEM>>>(xin, ea, ei, Wmsg + (size_t)t * NB * KD * INF_);
        k_aggr<<<(NN + 3) / 4, TPB>>>(xo);
        xin = xo;
    }

    k_readout<<<(NN + TPB - 1) / TPB, TPB>>>(xin, Wread, batch);
    k_mlp<<<1, TPB, MLP_SMEM>>>(fc1w, fc1b, fc2w, fc2b, fc3w, fc3b, out);
}

// round 3
// speedup vs baseline: 1.4896x; 1.4493x over previous
#include <cuda_runtime.h>
#include <math.h>

// Problem constants (fixed shapes per metadata)
#define NN      20000
#define EE      160000
#define ETOT    (NN + EE)      // 180000 (edges + self loops)
#define INF_    64
#define EC      16
#define KD      80
#define TSTEPS  4
#define NB      10
#define NG      64
#define TM      128            // edges per tile
#define TPB     256
#define MIS     84             // smem row stride (bank-conflict-free for mma frags)
#define NTILES  ((ETOT + TM - 1) / TM)   // 1407 per bucket (upper bound)

#define MSG_SMEM ((64*MIS + TM*MIS) * 4 + 2 * TM * 4)
#define MLP_SMEM ((NG*10 + NG*128 + NG*64) * 4)

// ---------------- device scratch ----------------
__device__ int   g_deg[NN];
__device__ int   g_indeg[NN];
__device__ int   g_dptr[NN + 1];
__device__ int   g_dcur[NN];
__device__ int   g_dlist[EE];
__device__ int   g_cursor[NB];
__device__ int   g_perm2[NB * ETOT];        // fixed-capacity bucket regions
__device__ float g_msgs[(size_t)ETOT * INF_];
__device__ float g_xA[NN * INF_];
__device__ float g_xB[NN * INF_];
__device__ float g_pooled[NG * 10];

// ---------------- helpers ----------------
__device__ __forceinline__ unsigned f2tf32(float f) {
    unsigned u; asm("cvt.rna.tf32.f32 %0, %1;" : "=r"(u) : "f"(f)); return u;
}
__device__ __forceinline__ void mma_tf32(float* c, unsigned a0, unsigned a1, unsigned a2, unsigned a3,
                                         unsigned b0, unsigned b1) {
    asm volatile("mma.sync.aligned.m16n8k8.row.col.f32.tf32.tf32.f32 "
                 "{%0,%1,%2,%3}, {%4,%5,%6,%7}, {%8,%9}, {%0,%1,%2,%3};"
                 : "+f"(c[0]), "+f"(c[1]), "+f"(c[2]), "+f"(c[3])
                 : "r"(a0), "r"(a1), "r"(a2), "r"(a3), "r"(b0), "r"(b1));
}
__device__ __forceinline__ float sigf(float x) { return 1.f / (1.f + __expf(-x)); }

// ---------------- preprocessing ----------------
__global__ void k_init() {
    int i = blockIdx.x * blockDim.x + threadIdx.x;
    if (i < NN) { g_deg[i] = 0; g_indeg[i] = 0; g_dcur[i] = 0; }
    if (i < NB) g_cursor[i] = 0;
    if (i < NG * 10) g_pooled[i] = 0.f;
}

__global__ void k_deg(const int* __restrict__ ei) {
    int e = blockIdx.x * blockDim.x + threadIdx.x;
    if (e < EE) {
        atomicAdd(&g_deg[ei[e]], 1);
        atomicAdd(&g_indeg[ei[EE + e]], 1);
    }
}

__global__ void k_scatter2(const int* __restrict__ ei) {
    int e = blockIdx.x * blockDim.x + threadIdx.x;
    if (e < ETOT) {
        int s = (e < EE) ? ei[e] : (e - EE);
        int b = min(g_deg[s] + 1, NB) - 1;
        int pos = atomicAdd(&g_cursor[b], 1);
        g_perm2[b * ETOT + pos] = e;
    }
}

#define SCH 20
__global__ __launch_bounds__(1024) void k_dscan() {
    __shared__ int ssum[1024];
    int t = threadIdx.x;
    int lo = t * SCH, hi = min(lo + SCH, NN);
    int s = 0;
    for (int i = lo; i < hi; i++) s += g_indeg[i];
    ssum[t] = s;
    __syncthreads();
    for (int off = 1; off < 1024; off <<= 1) {
        int v = 0;
        if (t >= off) v = ssum[t - off];
        __syncthreads();
        if (t >= off) ssum[t] += v;
        __syncthreads();
    }
    int pre = (t == 0) ? 0 : ssum[t - 1];
    for (int i = lo; i < hi; i++) { g_dptr[i] = pre; pre += g_indeg[i]; }
    if (lo < NN && hi == NN) g_dptr[NN] = pre;
}

__global__ void k_dscatter(const int* __restrict__ ei) {
    int e = blockIdx.x * blockDim.x + threadIdx.x;
    if (e < EE) {
        int d = ei[EE + e];
        int pos = atomicAdd(&g_dcur[d], 1);
        g_dlist[g_dptr[d] + pos] = e;
    }
}

// ---------------- phase 1: grouped GEMM (tf32 tensor cores) ----------------
__global__ __launch_bounds__(TPB, 2) void k_msg(
    const float* __restrict__ xin, const float* __restrict__ ea,
    const int* __restrict__ ei, const float* __restrict__ Wt)  // [NB][KD][64]
{
    extern __shared__ unsigned sm[];
    unsigned* Wts = sm;                  // [64][MIS] transposed: Wts[c*MIS + k]
    unsigned* miS = sm + 64 * MIS;       // [TM][MIS]
    int* eS   = (int*)(miS + TM * MIS);
    int* srcS = eS + TM;

    const int tid = threadIdx.x;
    const int bucket = blockIdx.y;

    __shared__ int s_cnt;
    if (tid == 0) s_cnt = g_cursor[bucket];
    __syncthreads();
    const int cnt = s_cnt;
    const int base = blockIdx.x * TM;
    if (base >= cnt) return;

    // stage bucket weight, transposed + tf32-converted
    const float* Wg = Wt + bucket * KD * 64;
    #pragma unroll
    for (int i = tid; i < KD * 64; i += TPB) {
        int k = i >> 6, c = i & 63;
        Wts[c * MIS + k] = f2tf32(Wg[i]);
    }

    // edge metadata
    for (int r = tid; r < TM; r += TPB) {
        int e = -1, s = 0;
        if (base + r < cnt) {
            e = g_perm2[bucket * ETOT + base + r];
            s = (e < EE) ? ei[e] : (e - EE);
        }
        eS[r] = e; srcS[r] = s;
    }
    __syncthreads();

    // gather mi rows (tf32 bits): [x[src] 16xf4 | ea 4xf4]
    const float4* xin4 = (const float4*)xin;
    const float4* ea4  = (const float4*)ea;
    for (int idx = tid; idx < TM * 20; idx += TPB) {
        int r = idx / 20, q = idx - r * 20;
        int e = eS[r];
        float4 v = make_float4(0.f, 0.f, 0.f, 0.f);
        if (e >= 0) {
            if (q < 16)      v = xin4[srcS[r] * 16 + q];
            else if (e < EE) v = ea4[e * 4 + (q - 16)];
        }
        uint4 u = make_uint4(f2tf32(v.x), f2tf32(v.y), f2tf32(v.z), f2tf32(v.w));
        *(uint4*)(miS + r * MIS + q * 4) = u;
    }
    __syncthreads();

    // warp w: rows w*16..+15, all 64 cols; m16n8k8 tf32 mma
    const int warp = tid >> 5, lane = tid & 31;
    const int g = lane >> 2, tg = lane & 3;
    const int rowbase = warp * 16;

    float acc[8][4];
    #pragma unroll
    for (int n = 0; n < 8; n++)
        #pragma unroll
        for (int j = 0; j < 4; j++) acc[n][j] = 0.f;

    const unsigned* A0 = miS + (rowbase + g) * MIS + tg;
    const unsigned* A1 = A0 + 8 * MIS;
    const unsigned* Bb = Wts + g * MIS + tg;

    #pragma unroll 2
    for (int kc = 0; kc < 10; kc++) {
        const int ko = kc * 8;
        unsigned a0 = A0[ko], a2 = A0[ko + 4];
        unsigned a1 = A1[ko], a3 = A1[ko + 4];
        #pragma unroll
        for (int nc = 0; nc < 8; nc++) {
            const unsigned* Bp = Bb + nc * 8 * MIS + ko;
            mma_tf32(acc[nc], a0, a1, a2, a3, Bp[0], Bp[4]);
        }
    }

    // sigmoid + store per-edge messages
    const int r0 = rowbase + g, r1 = r0 + 8;
    const int e0 = eS[r0], e1 = eS[r1];
    #pragma unroll
    for (int nc = 0; nc < 8; nc++) {
        int coff = nc * 8 + tg * 2;
        if (e0 >= 0) {
            float2 v = make_float2(sigf(acc[nc][0]), sigf(acc[nc][1]));
            *(float2*)(g_msgs + (size_t)e0 * 64 + coff) = v;
        }
        if (e1 >= 0) {
            float2 v = make_float2(sigf(acc[nc][2]), sigf(acc[nc][3]));
            *(float2*)(g_msgs + (size_t)e1 * 64 + coff) = v;
        }
    }
}

// ---------------- phase 2: CSR aggregation (float4) ----------------
__global__ __launch_bounds__(TPB) void k_aggr(float* __restrict__ xout) {
    int node = blockIdx.x * 16 + (threadIdx.x >> 4);
    int l = threadIdx.x & 15;
    if (node >= NN) return;
    const float4* m4 = (const float4*)g_msgs;
    float4 s = m4[(size_t)(EE + node) * 16 + l];     // self loop
    int beg = g_dptr[node], end = g_dptr[node + 1];
    for (int i = beg; i < end; i++) {
        float4 v = m4[(size_t)g_dlist[i] * 16 + l];
        s.x += v.x; s.y += v.y; s.z += v.z; s.w += v.w;
    }
    ((float4*)xout)[node * 16 + l] = s;
}

// ---------------- readout ----------------
__global__ __launch_bounds__(TPB) void k_readout(
    const float* __restrict__ x, const float* __restrict__ Wread,
    const int* __restrict__ batch)
{
    __shared__ float Ws[TSTEPS * INF_ * 10];
    for (int i = threadIdx.x; i < TSTEPS * INF_ * 10; i += TPB) Ws[i] = Wread[i];
    __syncthreads();

    int n = blockIdx.x * blockDim.x + threadIdx.x;
    if (n >= NN) return;

    float xr[INF_];
    const float4* xp = (const float4*)(x + n * INF_);
    #pragma unroll
    for (int q = 0; q < INF_ / 4; q++) {
        float4 f = xp[q];
        xr[q*4+0] = f.x; xr[q*4+1] = f.y; xr[q*4+2] = f.z; xr[q*4+3] = f.w;
    }

    float accq[10];
    #pragma unroll
    for (int j = 0; j < 10; j++) accq[j] = 0.f;

    for (int t = 0; t < TSTEPS; t++) {
        float l[10];
        #pragma unroll
        for (int j = 0; j < 10; j++) l[j] = 0.f;
        const float* W = Ws + t * INF_ * 10;
        #pragma unroll 4
        for (int k = 0; k < INF_; k++) {
            float xv = xr[k];
            #pragma unroll
            for (int j = 0; j < 10; j++) l[j] += xv * W[k * 10 + j];
        }
        float m = l[0];
        #pragma unroll
        for (int j = 1; j < 10; j++) m = fmaxf(m, l[j]);
        float ssum = 0.f;
        #pragma unroll
        for (int j = 0; j < 10; j++) { l[j] = __expf(l[j] - m); ssum += l[j]; }
        float inv = 1.f / ssum;
        #pragma unroll
        for (int j = 0; j < 10; j++) accq[j] += l[j] * inv;
    }

    int g = batch[n];
    #pragma unroll
    for (int j = 0; j < 10; j++) atomicAdd(&g_pooled[g * 10 + j], accq[j]);
}

// ---------------- final MLP ----------------
__global__ __launch_bounds__(TPB) void k_mlp(
    const float* __restrict__ fc1w, const float* __restrict__ fc1b,
    const float* __restrict__ fc2w, const float* __restrict__ fc2b,
    const float* __restrict__ fc3w, const float* __restrict__ fc3b,
    float* __restrict__ out)
{
    extern __shared__ float smf[];
    float* P  = smf;
    float* H1 = P + NG * 10;
    float* H2 = H1 + NG * 128;
    int tid = threadIdx.x;

    for (int i = tid; i < NG * 10; i += TPB) P[i] = g_pooled[i];
    __syncthreads();

    for (int idx = tid; idx < NG * 128; idx += TPB) {
        int g = idx >> 7, j = idx & 127;
        float a = fc1b[j];
        #pragma unroll
        for (int k = 0; k < 10; k++) a += P[g * 10 + k] * fc1w[k * 128 + j];
        H1[idx] = a > 0.f ? a : 0.01f * a;
    }
    __syncthreads();

    for (int idx = tid; idx < NG * 64; idx += TPB) {
        int g = idx >> 6, j = idx & 63;
        float a = fc2b[j];
        #pragma unroll 8
        for (int k = 0; k < 128; k++) a += H1[g * 128 + k] * fc2w[k * 64 + j];
        H2[idx] = a > 0.f ? a : 0.01f * a;
    }
    __syncthreads();

    for (int g = tid; g < NG; g += TPB) {
        float a = fc3b[0];
        #pragma unroll 8
        for (int k = 0; k < 64; k++) a += H2[g * 64 + k] * fc3w[k];
        out[g] = a > 0.f ? a : 0.01f * a;
    }
}

// ---------------- launch ----------------
extern "C" void kernel_launch(void* const* d_in, const int* in_sizes, int n_in,
                              void* d_out, int out_size)
{
    const float* x     = (const float*)d_in[0];
    const float* ea    = (const float*)d_in[1];
    const float* Wmsg  = (const float*)d_in[2];
    const float* Wread = (const float*)d_in[3];
    const float* fc1w  = (const float*)d_in[4];
    const float* fc1b  = (const float*)d_in[5];
    const float* fc2w  = (const float*)d_in[6];
    const float* fc2b  = (const float*)d_in[7];
    const float* fc3w  = (const float*)d_in[8];
    const float* fc3b  = (const float*)d_in[9];
    const int*   ei    = (const int*)d_in[10];
    const int*   batch = (const int*)d_in[11];
    float* out = (float*)d_out;

    cudaFuncSetAttribute(k_msg, cudaFuncAttributeMaxDynamicSharedMemorySize, MSG_SMEM);
    cudaFuncSetAttribute(k_mlp, cudaFuncAttributeMaxDynamicSharedMemorySize, MLP_SMEM);

    void *pA = nullptr, *pB = nullptr;
    cudaGetSymbolAddress(&pA, g_xA);
    cudaGetSymbolAddress(&pB, g_xB);

    dim3 msgGrid(NTILES, NB);

    k_init<<<(NN + TPB - 1) / TPB, TPB>>>();                       // 0
    k_deg<<<(EE + TPB - 1) / TPB, TPB>>>(ei);                      // 1
    k_scatter2<<<(ETOT + TPB - 1) / TPB, TPB>>>(ei);               // 2
    k_msg<<<msgGrid, TPB, MSG_SMEM>>>(x, ea, ei, Wmsg);            // 3  <- ncu capture target
    k_dscan<<<1, 1024>>>();                                        // 4
    k_dscatter<<<(EE + TPB - 1) / TPB, TPB>>>(ei);                 // 5

    const float* xin = x;
    for (int t = 0; t < TSTEPS; t++) {
        if (t > 0)
            k_msg<<<msgGrid, TPB, MSG_SMEM>>>(xin, ea, ei, Wmsg + (size_t)t * NB * KD * INF_);
        float* xo = (t % 2 == 0) ? (float*)pB : (float*)pA;
        k_aggr<<<(NN + 15) / 16, TPB>>>(xo);
        xin = xo;
    }

    k_readout<<<(NN + TPB - 1) / TPB, TPB>>>(xin, Wread, batch);
    k_mlp<<<1, TPB, MLP_SMEM>>>(fc1w, fc1b, fc2w, fc2b, fc3w, fc3b, out);
}

// round 5
// speedup vs baseline: 1.5789x; 1.0599x over previous
#include <cuda_runtime.h>
#include <math.h>

// Problem constants
#define NN      20000
#define EE      160000
#define ETOT    (NN + EE)      // 180000
#define INF_    64
#define EC      16
#define KD      80
#define TSTEPS  4
#define NB      10
#define NG      64
#define TM      128            // edges per tile
#define TPB     256
#define MIS     84             // smem dword row stride (pad 80 -> 84)
#define NTILEC  ((ETOT + TM - 1) / TM + NB)   // compact grid upper bound

#define MSG_SMEM ((64*MIS + TM*MIS) * 4 + 2 * TM * 4)
#define MLP_SMEM ((NG*10 + NG*128 + NG*64) * 4)

// ---------------- device scratch ----------------
__device__ int   g_deg[NN];
__device__ int   g_indeg[NN];
__device__ int   g_dptr[NN + 1];
__device__ int   g_dcur[NN];
__device__ int   g_dlist[EE];
__device__ int   g_cursor[NB];
__device__ int   g_perm2[NB * ETOT];
__device__ float g_msgs[(size_t)ETOT * INF_];
__device__ float g_xA[NN * INF_];
__device__ float g_xB[NN * INF_];
__device__ float g_pooled[NG * 10];

// ---------------- helpers ----------------
__device__ __forceinline__ unsigned f2tf32(float f) {
    unsigned u; asm("cvt.rna.tf32.f32 %0, %1;" : "=r"(u) : "f"(f)); return u;
}
__device__ __forceinline__ void mma_tf32(float* c, unsigned a0, unsigned a1, unsigned a2, unsigned a3,
                                         unsigned b0, unsigned b1) {
    asm volatile("mma.sync.aligned.m16n8k8.row.col.f32.tf32.tf32.f32 "
                 "{%0,%1,%2,%3}, {%4,%5,%6,%7}, {%8,%9}, {%0,%1,%2,%3};"
                 : "+f"(c[0]), "+f"(c[1]), "+f"(c[2]), "+f"(c[3])
                 : "r"(a0), "r"(a1), "r"(a2), "r"(a3), "r"(b0), "r"(b1));
}
__device__ __forceinline__ float sigf(float x) { return 1.f / (1.f + __expf(-x)); }

// ---------------- preprocessing ----------------
__global__ void k_init() {
    int i = blockIdx.x * blockDim.x + threadIdx.x;
    if (i < NN) { g_deg[i] = 0; g_indeg[i] = 0; g_dcur[i] = 0; }
    if (i < NB) g_cursor[i] = 0;
    if (i < NG * 10) g_pooled[i] = 0.f;
}

__global__ void k_deg(const int* __restrict__ ei) {
    int e = blockIdx.x * blockDim.x + threadIdx.x;
    if (e < EE) {
        atomicAdd(&g_deg[ei[e]], 1);
        atomicAdd(&g_indeg[ei[EE + e]], 1);
    }
}

__global__ void k_scatter2(const int* __restrict__ ei) {
    int e = blockIdx.x * blockDim.x + threadIdx.x;
    if (e < ETOT) {
        int s = (e < EE) ? ei[e] : (e - EE);
        int b = min(g_deg[s] + 1, NB) - 1;
        int pos = atomicAdd(&g_cursor[b], 1);
        g_perm2[b * ETOT + pos] = e;
    }
}

#define SCH 20
__global__ __launch_bounds__(1024) void k_dscan() {
    __shared__ int ssum[1024];
    int t = threadIdx.x;
    int lo = t * SCH, hi = min(lo + SCH, NN);
    int s = 0;
    for (int i = lo; i < hi; i++) s += g_indeg[i];
    ssum[t] = s;
    __syncthreads();
    for (int off = 1; off < 1024; off <<= 1) {
        int v = 0;
        if (t >= off) v = ssum[t - off];
        __syncthreads();
        if (t >= off) ssum[t] += v;
        __syncthreads();
    }
    int pre = (t == 0) ? 0 : ssum[t - 1];
    for (int i = lo; i < hi; i++) { g_dptr[i] = pre; pre += g_indeg[i]; }
    if (lo < NN && hi == NN) g_dptr[NN] = pre;
}

__global__ void k_dscatter(const int* __restrict__ ei) {
    int e = blockIdx.x * blockDim.x + threadIdx.x;
    if (e < EE) {
        int d = ei[EE + e];
        int pos = atomicAdd(&g_dcur[d], 1);
        g_dlist[g_dptr[d] + pos] = e;
    }
}

// ---------------- phase 1: grouped GEMM (tf32 tensor cores) ----------------
// Paired smem layout: pos dwords hold (k, k+4) adjacent -> every MMA operand pair = one LDS.64
__global__ __launch_bounds__(TPB, 3) void k_msg(
    const float* __restrict__ xin, const float* __restrict__ ea,
    const int* __restrict__ ei, const float* __restrict__ Wt)  // [NB][KD][64]
{
    extern __shared__ unsigned sm[];
    unsigned* Wts = sm;                  // [64][40 pairs] stride MIS dwords
    unsigned* miS = sm + 64 * MIS;       // [TM][40 pairs] stride MIS dwords
    int* eS   = (int*)(miS + TM * MIS);
    int* srcS = eS + TM;

    const int tid = threadIdx.x;

    // resolve (bucket, tile) from compact block id
    __shared__ int scnt[NB];
    __shared__ int s_bucket, s_loc, s_cnt;
    if (tid < NB) scnt[tid] = g_cursor[tid];
    __syncthreads();
    if (tid == 0) {
        int acc = 0, b = -1, loc = 0, cnt = 0;
        #pragma unroll
        for (int i = 0; i < NB; i++) {
            int nt = (scnt[i] + TM - 1) >> 7;
            if (b < 0 && (int)blockIdx.x < acc + nt) { b = i; loc = blockIdx.x - acc; cnt = scnt[i]; }
            acc += nt;
        }
        s_bucket = b; s_loc = loc; s_cnt = cnt;
    }
    __syncthreads();
    const int bucket = s_bucket;
    if (bucket < 0) return;
    const int cnt  = s_cnt;
    const int base = s_loc * TM;

    // stage bucket weight: Wts[c][pair] = (W[kc*8+j][c], W[kc*8+j+4][c])
    const float* Wg = Wt + bucket * KD * 64;
    #pragma unroll
    for (int idx = tid; idx < 64 * 40; idx += TPB) {
        int c = idx & 63, pair = idx >> 6;
        int kc = pair >> 2, j = pair & 3;
        int r0 = kc * 8 + j;
        uint2 u = make_uint2(f2tf32(Wg[r0 * 64 + c]), f2tf32(Wg[(r0 + 4) * 64 + c]));
        *(uint2*)(Wts + c * MIS + pair * 2) = u;
    }

    // edge metadata
    for (int r = tid; r < TM; r += TPB) {
        int e = -1, s = 0;
        if (base + r < cnt) {
            e = g_perm2[bucket * ETOT + base + r];
            s = (e < EE) ? ei[e] : (e - EE);
        }
        eS[r] = e; srcS[r] = s;
    }
    __syncthreads();

    // gather mi rows in k-chunks of 8, store as (k,k+4) pairs
    const float4* xin4 = (const float4*)xin;
    const float4* ea4  = (const float4*)ea;
    for (int idx = tid; idx < TM * 10; idx += TPB) {
        int r = idx / 10, kc = idx - r * 10;
        int e = eS[r];
        float4 v0 = make_float4(0.f,0.f,0.f,0.f), v1 = v0;
        if (e >= 0) {
            if (kc < 8)      { v0 = xin4[srcS[r] * 16 + kc * 2];     v1 = xin4[srcS[r] * 16 + kc * 2 + 1]; }
            else if (e < EE) { v0 = ea4[e * 4 + (kc - 8) * 2];       v1 = ea4[e * 4 + (kc - 8) * 2 + 1]; }
        }
        unsigned* p = miS + r * MIS + kc * 8;
        *(uint2*)(p + 0) = make_uint2(f2tf32(v0.x), f2tf32(v1.x));
        *(uint2*)(p + 2) = make_uint2(f2tf32(v0.y), f2tf32(v1.y));
        *(uint2*)(p + 4) = make_uint2(f2tf32(v0.z), f2tf32(v1.z));
        *(uint2*)(p + 6) = make_uint2(f2tf32(v0.w), f2tf32(v1.w));
    }
    __syncthreads();

    // warp w: rows w*16..+15, all 64 cols
    const int warp = tid >> 5, lane = tid & 31;
    const int g = lane >> 2, tg = lane & 3;
    const int rowbase = warp * 16;

    float acc[8][4];
    #pragma unroll
    for (int n = 0; n < 8; n++)
        #pragma unroll
        for (int j = 0; j < 4; j++) acc[n][j] = 0.f;

    const unsigned* A0 = miS + (rowbase + g) * MIS + tg * 2;
    const unsigned* A1 = A0 + 8 * MIS;
    const unsigned* Bb = Wts + g * MIS + tg * 2;

    #pragma unroll 2
    for (int kc = 0; kc < 10; kc++) {
        const int ko = kc * 8;
        uint2 pa0 = *(const uint2*)(A0 + ko);   // (a0, a2)
        uint2 pa1 = *(const uint2*)(A1 + ko);   // (a1, a3)
        #pragma unroll
        for (int nc = 0; nc < 8; nc++) {
            uint2 pb = *(const uint2*)(Bb + nc * 8 * MIS + ko);  // (b0, b1)
            mma_tf32(acc[nc], pa0.x, pa1.x, pa0.y, pa1.y, pb.x, pb.y);
        }
    }

    // sigmoid + store per-edge messages
    const int r0 = rowbase + g, r1 = r0 + 8;
    const int e0 = eS[r0], e1 = eS[r1];
    #pragma unroll
    for (int nc = 0; nc < 8; nc++) {
        int coff = nc * 8 + tg * 2;
        if (e0 >= 0) {
            float2 v = make_float2(sigf(acc[nc][0]), sigf(acc[nc][1]));
            *(float2*)(g_msgs + (size_t)e0 * 64 + coff) = v;
        }
        if (e1 >= 0) {
            float2 v = make_float2(sigf(acc[nc][2]), sigf(acc[nc][3]));
            *(float2*)(g_msgs + (size_t)e1 * 64 + coff) = v;
        }
    }
}

// ---------------- phase 2: CSR aggregation ----------------
__global__ __launch_bounds__(TPB) void k_aggr(float* __restrict__ xout) {
    int node = blockIdx.x * 16 + (threadIdx.x >> 4);
    int l = threadIdx.x & 15;
    if (node >= NN) return;
    const float4* m4 = (const float4*)g_msgs;
    float4 s = m4[(size_t)(EE + node) * 16 + l];
    int beg = g_dptr[node], end = g_dptr[node + 1];
    for (int i = beg; i < end; i++) {
        float4 v = m4[(size_t)g_dlist[i] * 16 + l];
        s.x += v.x; s.y += v.y; s.z += v.z; s.w += v.w;
    }
    ((float4*)xout)[node * 16 + l] = s;
}

// ---------------- readout ----------------
__global__ __launch_bounds__(TPB) void k_readout(
    const float* __restrict__ x, const float* __restrict__ Wread,
    const int* __restrict__ batch)
{
    __shared__ float Ws[TSTEPS * INF_ * 10];
    for (int i = threadIdx.x; i < TSTEPS * INF_ * 10; i += TPB) Ws[i] = Wread[i];
    __syncthreads();

    int n = blockIdx.x * blockDim.x + threadIdx.x;
    if (n >= NN) return;

    float xr[INF_];
    const float4* xp = (const float4*)(x + n * INF_);
    #pragma unroll
    for (int q = 0; q < INF_ / 4; q++) {
        float4 f = xp[q];
        xr[q*4+0] = f.x; xr[q*4+1] = f.y; xr[q*4+2] = f.z; xr[q*4+3] = f.w;
    }

    float accq[10];
    #pragma unroll
    for (int j = 0; j < 10; j++) accq[j] = 0.f;

    for (int t = 0; t < TSTEPS; t++) {
        float l[10];
        #pragma unroll
        for (int j = 0; j < 10; j++) l[j] = 0.f;
        const float* W = Ws + t * INF_ * 10;
        #pragma unroll 4
        for (int k = 0; k < INF_; k++) {
            float xv = xr[k];
            #pragma unroll
            for (int j = 0; j < 10; j++) l[j] += xv * W[k * 10 + j];
        }
        float m = l[0];
        #pragma unroll
        for (int j = 1; j < 10; j++) m = fmaxf(m, l[j]);
        float ssum = 0.f;
        #pragma unroll
        for (int j = 0; j < 10; j++) { l[j] = __expf(l[j] - m); ssum += l[j]; }
        float inv = 1.f / ssum;
        #pragma unroll
        for (int j = 0; j < 10; j++) accq[j] += l[j] * inv;
    }

    int g = batch[n];
    #pragma unroll
    for (int j = 0; j < 10; j++) atomicAdd(&g_pooled[g * 10 + j], accq[j]);
}

// ---------------- final MLP ----------------
__global__ __launch_bounds__(TPB) void k_mlp(
    const float* __restrict__ fc1w, const float* __restrict__ fc1b,
    const float* __restrict__ fc2w, const float* __restrict__ fc2b,
    const float* __restrict__ fc3w, const float* __restrict__ fc3b,
    float* __restrict__ out)
{
    extern __shared__ float smf[];
    float* P  = smf;
    float* H1 = P + NG * 10;
    float* H2 = H1 + NG * 128;
    int tid = threadIdx.x;

    for (int i = tid; i < NG * 10; i += TPB) P[i] = g_pooled[i];
    __syncthreads();

    for (int idx = tid; idx < NG * 128; idx += TPB) {
        int g = idx >> 7, j = idx & 127;
        float a = fc1b[j];
        #pragma unroll
        for (int k = 0; k < 10; k++) a += P[g * 10 + k] * fc1w[k * 128 + j];
        H1[idx] = a > 0.f ? a : 0.01f * a;
    }
    __syncthreads();

    for (int idx = tid; idx < NG * 64; idx += TPB) {
        int g = idx >> 6, j = idx & 63;
        float a = fc2b[j];
        #pragma unroll 8
        for (int k = 0; k < 128; k++) a += H1[g * 128 + k] * fc2w[k * 64 + j];
        H2[idx] = a > 0.f ? a : 0.01f * a;
    }
    __syncthreads();

    for (int g = tid; g < NG; g += TPB) {
        float a = fc3b[0];
        #pragma unroll 8
        for (int k = 0; k < 64; k++) a += H2[g * 64 + k] * fc3w[k];
        out[g] = a > 0.f ? a : 0.01f * a;
    }
}

// ---------------- launch ----------------
extern "C" void kernel_launch(void* const* d_in, const int* in_sizes, int n_in,
                              void* d_out, int out_size)
{
    const float* x     = (const float*)d_in[0];
    const float* ea    = (const float*)d_in[1];
    const float* Wmsg  = (const float*)d_in[2];
    const float* Wread = (const float*)d_in[3];
    const float* fc1w  = (const float*)d_in[4];
    const float* fc1b  = (const float*)d_in[5];
    const float* fc2w  = (const float*)d_in[6];
    const float* fc2b  = (const float*)d_in[7];
    const float* fc3w  = (const float*)d_in[8];
    const float* fc3b  = (const float*)d_in[9];
    const int*   ei    = (const int*)d_in[10];
    const int*   batch = (const int*)d_in[11];
    float* out = (float*)d_out;

    cudaFuncSetAttribute(k_msg, cudaFuncAttributeMaxDynamicSharedMemorySize, MSG_SMEM);
    cudaFuncSetAttribute(k_mlp, cudaFuncAttributeMaxDynamicSharedMemorySize, MLP_SMEM);

    void *pA = nullptr, *pB = nullptr;
    cudaGetSymbolAddress(&pA, g_xA);
    cudaGetSymbolAddress(&pB, g_xB);

    k_init<<<(NN + TPB - 1) / TPB, TPB>>>();                       // 0
    k_deg<<<(EE + TPB - 1) / TPB, TPB>>>(ei);                      // 1
    k_scatter2<<<(ETOT + TPB - 1) / TPB, TPB>>>(ei);               // 2
    k_msg<<<NTILEC, TPB, MSG_SMEM>>>(x, ea, ei, Wmsg);             // 3  <- ncu capture target
    k_dscan<<<1, 1024>>>();                                        // 4
    k_dscatter<<<(EE + TPB - 1) / TPB, TPB>>>(ei);                 // 5

    const float* xin = x;
    for (int t = 0; t < TSTEPS; t++) {
        if (t > 0)
            k_msg<<<NTILEC, TPB, MSG_SMEM>>>(xin, ea, ei, Wmsg + (size_t)t * NB * KD * INF_);
        float* xo = (t % 2 == 0) ? (float*)pB : (float*)pA;
        k_aggr<<<(NN + 15) / 16, TPB>>>(xo);
        xin = xo;
    }

    k_readout<<<(NN + TPB - 1) / TPB, TPB>>>(xin, Wread, batch);
    k_mlp<<<1, TPB, MLP_SMEM>>>(fc1w, fc1b, fc2w, fc2b, fc3w, fc3b, out);
}

// round 6
// speedup vs baseline: 1.7163x; 1.0871x over previous
#include <cuda_runtime.h>
#include <math.h>

// Problem constants
#define NN      20000
#define EE      160000
#define ETOT    (NN + EE)
#define INF_    64
#define EC      16
#define KD      80
#define TSTEPS  4
#define NB      10
#define NG      64
#define TM      128
#define TPB     256
#define NIS     68            // node-GEMM smem dword row stride (64 + pad)
#define EIS     20            // edge-GEMM smem dword row stride (16 + pad)
#define NTILEN  ((NN + TM - 1) / TM + NB)   // 167
#define NTILEE  ((EE + TM - 1) / TM + NB)   // 1260

#define NODE_SMEM ((64*NIS + TM*NIS) * 4 + TM * 4)
#define EDGE_SMEM ((64*EIS + TM*EIS) * 4 + 3 * TM * 4)
#define MLP_SMEM  ((NG*10 + NG*128 + NG*64) * 4)

// ---------------- device scratch ----------------
__device__ int   g_deg[NN];
__device__ int   g_indeg[NN];
__device__ int   g_dptr[NN + 1];
__device__ int   g_dcur[NN];
__device__ int   g_dpos[EE];
__device__ int   g_cursor[NB];         // edge-bucket counts
__device__ int   g_ncursor[NB];        // node-bucket counts
__device__ int   g_perm2[NB * ETOT];   // edges grouped by src bucket
__device__ int   g_nperm[NB * NN];     // nodes grouped by bucket
__device__ float g_y[NN * INF_];       // per-node x @ W_top
__device__ float g_msgs[(size_t)EE * INF_];   // per-edge messages in dst-CSR order
__device__ float g_xA[NN * INF_];
__device__ float g_xB[NN * INF_];
__device__ float g_pooled[NG * 10];

// ---------------- helpers ----------------
__device__ __forceinline__ unsigned f2tf32(float f) {
    unsigned u; asm("cvt.rna.tf32.f32 %0, %1;" : "=r"(u) : "f"(f)); return u;
}
__device__ __forceinline__ void mma_tf32(float* c, unsigned a0, unsigned a1, unsigned a2, unsigned a3,
                                         unsigned b0, unsigned b1) {
    asm volatile("mma.sync.aligned.m16n8k8.row.col.f32.tf32.tf32.f32 "
                 "{%0,%1,%2,%3}, {%4,%5,%6,%7}, {%8,%9}, {%0,%1,%2,%3};"
                 : "+f"(c[0]), "+f"(c[1]), "+f"(c[2]), "+f"(c[3])
                 : "r"(a0), "r"(a1), "r"(a2), "r"(a3), "r"(b0), "r"(b1));
}
__device__ __forceinline__ float sigf(float x) { return 1.f / (1.f + __expf(-x)); }

// ---------------- preprocessing ----------------
__global__ void k_init() {
    int i = blockIdx.x * blockDim.x + threadIdx.x;
    if (i < NN) { g_deg[i] = 0; g_indeg[i] = 0; g_dcur[i] = 0; }
    if (i < NB) { g_cursor[i] = 0; g_ncursor[i] = 0; }
    if (i < NG * 10) g_pooled[i] = 0.f;
}

__global__ void k_deg(const int* __restrict__ ei) {
    int e = blockIdx.x * blockDim.x + threadIdx.x;
    if (e < EE) {
        atomicAdd(&g_deg[ei[e]], 1);
        atomicAdd(&g_indeg[ei[EE + e]], 1);
    }
}

__global__ void k_nscatter() {
    int n = blockIdx.x * blockDim.x + threadIdx.x;
    if (n < NN) {
        int b = min(g_deg[n] + 1, NB) - 1;
        int pos = atomicAdd(&g_ncursor[b], 1);
        g_nperm[b * NN + pos] = n;
    }
}

__global__ void k_scatter2(const int* __restrict__ ei) {
    int e = blockIdx.x * blockDim.x + threadIdx.x;
    if (e < EE) {
        int b = min(g_deg[ei[e]] + 1, NB) - 1;
        int pos = atomicAdd(&g_cursor[b], 1);
        g_perm2[b * ETOT + pos] = e;
    }
}

#define SCH 20
__global__ __launch_bounds__(1024) void k_dscan() {
    __shared__ int ssum[1024];
    int t = threadIdx.x;
    int lo = t * SCH, hi = min(lo + SCH, NN);
    int s = 0;
    for (int i = lo; i < hi; i++) s += g_indeg[i];
    ssum[t] = s;
    __syncthreads();
    for (int off = 1; off < 1024; off <<= 1) {
        int v = 0;
        if (t >= off) v = ssum[t - off];
        __syncthreads();
        if (t >= off) ssum[t] += v;
        __syncthreads();
    }
    int pre = (t == 0) ? 0 : ssum[t - 1];
    for (int i = lo; i < hi; i++) { g_dptr[i] = pre; pre += g_indeg[i]; }
    if (lo < NN && hi == NN) g_dptr[NN] = pre;
}

__global__ void k_dscatter(const int* __restrict__ ei) {
    int e = blockIdx.x * blockDim.x + threadIdx.x;
    if (e < EE) {
        int d = ei[EE + e];
        int pos = atomicAdd(&g_dcur[d], 1);
        g_dpos[e] = g_dptr[d] + pos;
    }
}

// ---------------- node GEMM: y = x @ W_top[bucket(n)]  (K=64) ----------------
__global__ __launch_bounds__(TPB, 4) void k_node(
    const float* __restrict__ xin, const float* __restrict__ Wt)  // [NB][KD][64]
{
    extern __shared__ unsigned sm[];
    unsigned* Wts = sm;                  // [64][32 pairs] stride NIS
    unsigned* A   = sm + 64 * NIS;       // [TM][32 pairs] stride NIS
    int* nidS = (int*)(A + TM * NIS);

    const int tid = threadIdx.x;
    __shared__ int scnt[NB];
    __shared__ int s_bucket, s_loc, s_cnt;
    if (tid < NB) scnt[tid] = g_ncursor[tid];
    __syncthreads();
    if (tid == 0) {
        int acc = 0, b = -1, loc = 0, cnt = 0;
        #pragma unroll
        for (int i = 0; i < NB; i++) {
            int nt = (scnt[i] + TM - 1) >> 7;
            if (b < 0 && (int)blockIdx.x < acc + nt) { b = i; loc = blockIdx.x - acc; cnt = scnt[i]; }
            acc += nt;
        }
        s_bucket = b; s_loc = loc; s_cnt = cnt;
    }
    __syncthreads();
    const int bucket = s_bucket;
    if (bucket < 0) return;
    const int cnt  = s_cnt;
    const int base = s_loc * TM;

    // stage W_top (rows 0..63) paired
    const float* Wg = Wt + bucket * KD * 64;
    #pragma unroll
    for (int idx = tid; idx < 64 * 32; idx += TPB) {
        int c = idx & 63, p = idx >> 6;
        int kc = p >> 2, j = p & 3;
        int r0 = kc * 8 + j;
        uint2 u = make_uint2(f2tf32(Wg[r0 * 64 + c]), f2tf32(Wg[(r0 + 4) * 64 + c]));
        *(uint2*)(Wts + c * NIS + p * 2) = u;
    }

    for (int r = tid; r < TM; r += TPB)
        nidS[r] = (base + r < cnt) ? g_nperm[bucket * NN + base + r] : -1;
    __syncthreads();

    // gather x rows paired
    const float4* xin4 = (const float4*)xin;
    for (int idx = tid; idx < TM * 8; idx += TPB) {
        int r = idx >> 3, kc = idx & 7;
        int nid = nidS[r];
        float4 v0 = make_float4(0.f,0.f,0.f,0.f), v1 = v0;
        if (nid >= 0) { v0 = xin4[nid * 16 + kc * 2]; v1 = xin4[nid * 16 + kc * 2 + 1]; }
        unsigned* p = A + r * NIS + kc * 8;
        *(uint2*)(p + 0) = make_uint2(f2tf32(v0.x), f2tf32(v1.x));
        *(uint2*)(p + 2) = make_uint2(f2tf32(v0.y), f2tf32(v1.y));
        *(uint2*)(p + 4) = make_uint2(f2tf32(v0.z), f2tf32(v1.z));
        *(uint2*)(p + 6) = make_uint2(f2tf32(v0.w), f2tf32(v1.w));
    }
    __syncthreads();

    const int warp = tid >> 5, lane = tid & 31;
    const int g = lane >> 2, tg = lane & 3;
    const int rowbase = warp * 16;

    float acc[8][4];
    #pragma unroll
    for (int n = 0; n < 8; n++)
        #pragma unroll
        for (int j = 0; j < 4; j++) acc[n][j] = 0.f;

    const unsigned* A0 = A + (rowbase + g) * NIS + tg * 2;
    const unsigned* A1 = A0 + 8 * NIS;
    const unsigned* Bb = Wts + g * NIS + tg * 2;

    #pragma unroll 2
    for (int kc = 0; kc < 8; kc++) {
        const int ko = kc * 8;
        uint2 pa0 = *(const uint2*)(A0 + ko);
        uint2 pa1 = *(const uint2*)(A1 + ko);
        #pragma unroll
        for (int nc = 0; nc < 8; nc++) {
            uint2 pb = *(const uint2*)(Bb + nc * 8 * NIS + ko);
            mma_tf32(acc[nc], pa0.x, pa1.x, pa0.y, pa1.y, pb.x, pb.y);
        }
    }

    const int r0 = rowbase + g, r1 = r0 + 8;
    const int n0 = nidS[r0], n1 = nidS[r1];
    #pragma unroll
    for (int nc = 0; nc < 8; nc++) {
        int coff = nc * 8 + tg * 2;
        if (n0 >= 0) *(float2*)(g_y + n0 * 64 + coff) = make_float2(acc[nc][0], acc[nc][1]);
        if (n1 >= 0) *(float2*)(g_y + n1 * 64 + coff) = make_float2(acc[nc][2], acc[nc][3]);
    }
}

// ---------------- edge GEMM: msg = sigmoid(y[src] + ea @ W_bot[b])  (K=16) ----------------
__global__ __launch_bounds__(TPB, 4) void k_edge(
    const float* __restrict__ ea, const int* __restrict__ ei,
    const float* __restrict__ Wt)
{
    extern __shared__ unsigned sm[];
    unsigned* Wts = sm;                  // [64][8 pairs] stride EIS
    unsigned* A   = sm + 64 * EIS;       // [TM][8 pairs] stride EIS
    int* eS    = (int*)(A + TM * EIS);
    int* srcS  = eS + TM;
    int* dposS = srcS + TM;

    const int tid = threadIdx.x;
    __shared__ int scnt[NB];
    __shared__ int s_bucket, s_loc, s_cnt;
    if (tid < NB) scnt[tid] = g_cursor[tid];
    __syncthreads();
    if (tid == 0) {
        int acc = 0, b = -1, loc = 0, cnt = 0;
        #pragma unroll
        for (int i = 0; i < NB; i++) {
            int nt = (scnt[i] + TM - 1) >> 7;
            if (b < 0 && (int)blockIdx.x < acc + nt) { b = i; loc = blockIdx.x - acc; cnt = scnt[i]; }
            acc += nt;
        }
        s_bucket = b; s_loc = loc; s_cnt = cnt;
    }
    __syncthreads();
    const int bucket = s_bucket;
    if (bucket < 0) return;
    const int cnt  = s_cnt;
    const int base = s_loc * TM;

    // stage W_bot (rows 64..79) paired
    const float* Wg = Wt + bucket * KD * 64;
    #pragma unroll
    for (int idx = tid; idx < 64 * 8; idx += TPB) {
        int c = idx & 63, p = idx >> 6;
        int kc = p >> 2, j = p & 3;
        int r0 = 64 + kc * 8 + j;
        uint2 u = make_uint2(f2tf32(Wg[r0 * 64 + c]), f2tf32(Wg[(r0 + 4) * 64 + c]));
        *(uint2*)(Wts + c * EIS + p * 2) = u;
    }

    for (int r = tid; r < TM; r += TPB) {
        int e = -1, s = 0, dp = 0;
        if (base + r < cnt) {
            e = g_perm2[bucket * ETOT + base + r];
            s = ei[e];
            dp = g_dpos[e];
        }
        eS[r] = e; srcS[r] = s; dposS[r] = dp;
    }
    __syncthreads();

    // gather ea rows paired (K=16 -> 2 kc chunks)
    const float4* ea4 = (const float4*)ea;
    for (int idx = tid; idx < TM * 2; idx += TPB) {
        int r = idx >> 1, kc = idx & 1;
        int e = eS[r];
        float4 v0 = make_float4(0.f,0.f,0.f,0.f), v1 = v0;
        if (e >= 0) { v0 = ea4[e * 4 + kc * 2]; v1 = ea4[e * 4 + kc * 2 + 1]; }
        unsigned* p = A + r * EIS + kc * 8;
        *(uint2*)(p + 0) = make_uint2(f2tf32(v0.x), f2tf32(v1.x));
        *(uint2*)(p + 2) = make_uint2(f2tf32(v0.y), f2tf32(v1.y));
        *(uint2*)(p + 4) = make_uint2(f2tf32(v0.z), f2tf32(v1.z));
        *(uint2*)(p + 6) = make_uint2(f2tf32(v0.w), f2tf32(v1.w));
    }
    __syncthreads();

    const int warp = tid >> 5, lane = tid & 31;
    const int g = lane >> 2, tg = lane & 3;
    const int rowbase = warp * 16;

    float acc[8][4];
    #pragma unroll
    for (int n = 0; n < 8; n++)
        #pragma unroll
        for (int j = 0; j < 4; j++) acc[n][j] = 0.f;

    const unsigned* A0 = A + (rowbase + g) * EIS + tg * 2;
    const unsigned* A1 = A0 + 8 * EIS;
    const unsigned* Bb = Wts + g * EIS + tg * 2;

    #pragma unroll
    for (int kc = 0; kc < 2; kc++) {
        const int ko = kc * 8;
        uint2 pa0 = *(const uint2*)(A0 + ko);
        uint2 pa1 = *(const uint2*)(A1 + ko);
        #pragma unroll
        for (int nc = 0; nc < 8; nc++) {
            uint2 pb = *(const uint2*)(Bb + nc * 8 * EIS + ko);
            mma_tf32(acc[nc], pa0.x, pa1.x, pa0.y, pa1.y, pb.x, pb.y);
        }
    }

    // epilogue: add y[src], sigmoid, store to dst-CSR slot
    const int r0 = rowbase + g, r1 = r0 + 8;
    const int e0 = eS[r0], e1 = eS[r1];
    const int s0 = srcS[r0], s1 = srcS[r1];
    const int p0 = dposS[r0], p1 = dposS[r1];
    #pragma unroll
    for (int nc = 0; nc < 8; nc++) {
        int coff = nc * 8 + tg * 2;
        if (e0 >= 0) {
            float2 yv = *(const float2*)(g_y + (size_t)s0 * 64 + coff);
            float2 v = make_float2(sigf(acc[nc][0] + yv.x), sigf(acc[nc][1] + yv.y));
            *(float2*)(g_msgs + (size_t)p0 * 64 + coff) = v;
        }
        if (e1 >= 0) {
            float2 yv = *(const float2*)(g_y + (size_t)s1 * 64 + coff);
            float2 v = make_float2(sigf(acc[nc][2] + yv.x), sigf(acc[nc][3] + yv.y));
            *(float2*)(g_msgs + (size_t)p1 * 64 + coff) = v;
        }
    }
}

// ---------------- aggregation: sequential CSR ranges + self message ----------------
__global__ __launch_bounds__(TPB) void k_aggr(float* __restrict__ xout) {
    int node = blockIdx.x * 16 + (threadIdx.x >> 4);
    int l = threadIdx.x & 15;
    if (node >= NN) return;
    const float4* y4 = (const float4*)g_y;
    float4 yv = y4[node * 16 + l];
    float4 s = make_float4(sigf(yv.x), sigf(yv.y), sigf(yv.z), sigf(yv.w));  // self loop
    const float4* m4 = (const float4*)g_msgs;
    int beg = g_dptr[node], end = g_dptr[node + 1];
    for (int i = beg; i < end; i++) {
        float4 v = m4[(size_t)i * 16 + l];
        s.x += v.x; s.y += v.y; s.z += v.z; s.w += v.w;
    }
    ((float4*)xout)[node * 16 + l] = s;
}

// ---------------- readout ----------------
__global__ __launch_bounds__(TPB) void k_readout(
    const float* __restrict__ x, const float* __restrict__ Wread,
    const int* __restrict__ batch)
{
    __shared__ float Ws[TSTEPS * INF_ * 10];
    for (int i = threadIdx.x; i < TSTEPS * INF_ * 10; i += TPB) Ws[i] = Wread[i];
    __syncthreads();

    int n = blockIdx.x * blockDim.x + threadIdx.x;
    if (n >= NN) return;

    float xr[INF_];
    const float4* xp = (const float4*)(x + n * INF_);
    #pragma unroll
    for (int q = 0; q < INF_ / 4; q++) {
        float4 f = xp[q];
        xr[q*4+0] = f.x; xr[q*4+1] = f.y; xr[q*4+2] = f.z; xr[q*4+3] = f.w;
    }

    float accq[10];
    #pragma unroll
    for (int j = 0; j < 10; j++) accq[j] = 0.f;

    for (int t = 0; t < TSTEPS; t++) {
        float l[10];
        #pragma unroll
        for (int j = 0; j < 10; j++) l[j] = 0.f;
        const float* W = Ws + t * INF_ * 10;
        #pragma unroll 4
        for (int k = 0; k < INF_; k++) {
            float xv = xr[k];
            #pragma unroll
            for (int j = 0; j < 10; j++) l[j] += xv * W[k * 10 + j];
        }
        float m = l[0];
        #pragma unroll
        for (int j = 1; j < 10; j++) m = fmaxf(m, l[j]);
        float ssum = 0.f;
        #pragma unroll
        for (int j = 0; j < 10; j++) { l[j] = __expf(l[j] - m); ssum += l[j]; }
        float inv = 1.f / ssum;
        #pragma unroll
        for (int j = 0; j < 10; j++) accq[j] += l[j] * inv;
    }

    int g = batch[n];
    #pragma unroll
    for (int j = 0; j < 10; j++) atomicAdd(&g_pooled[g * 10 + j], accq[j]);
}

// ---------------- final MLP ----------------
__global__ __launch_bounds__(TPB) void k_mlp(
    const float* __restrict__ fc1w, const float* __restrict__ fc1b,
    const float* __restrict__ fc2w, const float* __restrict__ fc2b,
    const float* __restrict__ fc3w, const float* __restrict__ fc3b,
    float* __restrict__ out)
{
    extern __shared__ float smf[];
    float* P  = smf;
    float* H1 = P + NG * 10;
    float* H2 = H1 + NG * 128;
    int tid = threadIdx.x;

    for (int i = tid; i < NG * 10; i += TPB) P[i] = g_pooled[i];
    __syncthreads();

    for (int idx = tid; idx < NG * 128; idx += TPB) {
        int g = idx >> 7, j = idx & 127;
        float a = fc1b[j];
        #pragma unroll
        for (int k = 0; k < 10; k++) a += P[g * 10 + k] * fc1w[k * 128 + j];
        H1[idx] = a > 0.f ? a : 0.01f * a;
    }
    __syncthreads();

    for (int idx = tid; idx < NG * 64; idx += TPB) {
        int g = idx >> 6, j = idx & 63;
        float a = fc2b[j];
        #pragma unroll 8
        for (int k = 0; k < 128; k++) a += H1[g * 128 + k] * fc2w[k * 64 + j];
        H2[idx] = a > 0.f ? a : 0.01f * a;
    }
    __syncthreads();

    for (int g = tid; g < NG; g += TPB) {
        float a = fc3b[0];
        #pragma unroll 8
        for (int k = 0; k < 64; k++) a += H2[g * 64 + k] * fc3w[k];
        out[g] = a > 0.f ? a : 0.01f * a;
    }
}

// ---------------- launch ----------------
extern "C" void kernel_launch(void* const* d_in, const int* in_sizes, int n_in,
                              void* d_out, int out_size)
{
    const float* x     = (const float*)d_in[0];
    const float* ea    = (const float*)d_in[1];
    const float* Wmsg  = (const float*)d_in[2];
    const float* Wread = (const float*)d_in[3];
    const float* fc1w  = (const float*)d_in[4];
    const float* fc1b  = (const float*)d_in[5];
    const float* fc2w  = (const float*)d_in[6];
    const float* fc2b  = (const float*)d_in[7];
    const float* fc3w  = (const float*)d_in[8];
    const float* fc3b  = (const float*)d_in[9];
    const int*   ei    = (const int*)d_in[10];
    const int*   batch = (const int*)d_in[11];
    float* out = (float*)d_out;

    cudaFuncSetAttribute(k_node, cudaFuncAttributeMaxDynamicSharedMemorySize, NODE_SMEM);
    cudaFuncSetAttribute(k_edge, cudaFuncAttributeMaxDynamicSharedMemorySize, EDGE_SMEM);
    cudaFuncSetAttribute(k_mlp,  cudaFuncAttributeMaxDynamicSharedMemorySize, MLP_SMEM);

    void *pA = nullptr, *pB = nullptr;
    cudaGetSymbolAddress(&pA, g_xA);
    cudaGetSymbolAddress(&pB, g_xB);

    k_init<<<(NN + TPB - 1) / TPB, TPB>>>();                        // 0
    k_deg<<<(EE + TPB - 1) / TPB, TPB>>>(ei);                       // 1
    k_nscatter<<<(NN + TPB - 1) / TPB, TPB>>>();                    // 2
    k_node<<<NTILEN, TPB, NODE_SMEM>>>(x, Wmsg);                    // 3  <- ncu capture target
    k_scatter2<<<(EE + TPB - 1) / TPB, TPB>>>(ei);                  // 4
    k_dscan<<<1, 1024>>>();                                         // 5
    k_dscatter<<<(EE + TPB - 1) / TPB, TPB>>>(ei);                  // 6

    const float* xin = x;
    for (int t = 0; t < TSTEPS; t++) {
        const float* Wt = Wmsg + (size_t)t * NB * KD * INF_;
        if (t > 0)
            k_node<<<NTILEN, TPB, NODE_SMEM>>>(xin, Wt);
        k_edge<<<NTILEE, TPB, EDGE_SMEM>>>(ea, ei, Wt);
        float* xo = (t % 2 == 0) ? (float*)pB : (float*)pA;
        k_aggr<<<(NN + 15) / 16, TPB>>>(xo);
        xin = xo;
    }

    k_readout<<<(NN + TPB - 1) / TPB, TPB>>>(xin, Wread, batch);
    k_mlp<<<1, TPB, MLP_SMEM>>>(fc1w, fc1b, fc2w, fc2b, fc3w, fc3b, out);
}